// round 10
// baseline (speedup 1.0000x reference)
#include <cuda_runtime.h>
#include <math.h>

#define NLEV 16
#define RESO 2048
#define PRIME_Y 2654435761u
#define SF_STRIDE 18   // u64 per thread row: 16 levels + 2 pad -> 144B rows, 16B aligned

struct Levels {
    float    scale[NLEV];
    unsigned res[NLEV];
    unsigned size[NLEV];
    unsigned offset[NLEV];
    unsigned hashed[NLEV];
};

typedef unsigned long long u64;

__constant__ float cW0[64 * 32];   // [j][i] row-major
__constant__ float cW1t[64 * 8];   // transposed: [j][k]
__device__   float g_w1t[64 * 8];  // staging for the transpose

__device__ __forceinline__ u64 pk2(float lo, float hi) {
    u64 r; asm("mov.b64 %0,{%1,%2};" : "=l"(r) : "f"(lo), "f"(hi)); return r;
}
__device__ __forceinline__ float2 upk2(u64 a) {
    float2 f; asm("mov.b64 {%0,%1},%2;" : "=f"(f.x), "=f"(f.y) : "l"(a)); return f;
}
__device__ __forceinline__ u64 ffma2(u64 a, u64 b, u64 c) {
    u64 d; asm("fma.rn.f32x2 %0,%1,%2,%3;" : "=l"(d) : "l"(a), "l"(b), "l"(c)); return d;
}
__device__ __forceinline__ u64 mul2(u64 a, u64 b) {
    u64 d; asm("mul.rn.f32x2 %0,%1,%2;" : "=l"(d) : "l"(a), "l"(b)); return d;
}

__device__ __forceinline__ float decode_bound(const unsigned* p, int elems) {
    if (!p || elems <= 0) return 1.0f;
    unsigned a = p[0];
    float ff = __uint_as_float(a);
    if (isfinite(ff) && fabsf(ff) > 1e-6f && fabsf(ff) < 1e9f) return ff;
    int ai = (int)a;
    if (ai != 0 && ai > -1000000000 && ai < 1000000000) return (float)ai;
    if (elems >= 2) {
        double d = __hiloint2double((int)p[1], (int)a);
        if (isfinite(d) && fabs(d) > 1e-6 && fabs(d) < 1e9) return (float)d;
    }
    return 1.0f;
}

__global__ void transpose_w1(const float* __restrict__ w1) {
    int i = threadIdx.x;             // 512 threads
    int k = i >> 6, j = i & 63;
    g_w1t[j * 8 + k] = w1[i];
}

__global__ __launch_bounds__(128, 4)
void plane_kernel(const float2* __restrict__ xy,
                  const float2* __restrict__ table,
                  const unsigned* __restrict__ bound_raw,
                  int bound_elems,
                  float* __restrict__ out,
                  int N, Levels L)
{
    // Per-thread feature rows for corners c and d in shared memory; combined
    // with the (128,4) launch bound this yields 4 blocks/SM (16 warps) so the
    // fma pipe has enough warps to cover gather latency.
    __shared__ __align__(16) u64 sFc[128 * SF_STRIDE];
    __shared__ __align__(16) u64 sFd[128 * SF_STRIDE];

    int n = blockIdx.x * blockDim.x + threadIdx.x;
    if (n >= N) return;

    u64* mFc = &sFc[threadIdx.x * SF_STRIDE];
    u64* mFd = &sFd[threadIdx.x * SF_STRIDE];

    float bound = decode_bound(bound_raw, bound_elems);

    float2 p = xy[n];
    float inv2b = 0.5f / bound;
    float nxv = (p.x + bound) * inv2b;
    float nyv = (p.y + bound) * inv2b;
    float cx = fminf(fmaxf(nxv * (float)RESO - 0.5f, 0.0f), (float)(RESO - 1));
    float cy = fminf(fmaxf(nyv * (float)RESO - 0.5f, 0.0f), (float)(RESO - 1));
    float cx0 = floorf(cx), cy0 = floorf(cy);
    float cx1 = fminf(cx0 + 1.0f, (float)(RESO - 1));
    float cy1 = fminf(cy0 + 1.0f, (float)(RESO - 1));
    float u = cx - cx0, v = cy - cy0;

    float gx0 = (cx0 + 0.5f) * (1.0f / (float)RESO);
    float gx1 = (cx1 + 0.5f) * (1.0f / (float)RESO);
    float gyA = (cy0 + 0.5f) * (1.0f / (float)RESO);
    float gyB = (cy1 + 0.5f) * (1.0f / (float)RESO);

    // Features for corners a=(x0,y0), b=(x1,y0) in registers; c=(x0,y1),
    // d=(x1,y1) in shared.
    u64 Fa[NLEV], Fb[NLEV];

    #pragma unroll
    for (int l = 0; l < NLEV; l++) {
        float    scale  = L.scale[l];
        unsigned res    = L.res[l];
        unsigned size   = L.size[l];
        unsigned off    = L.offset[l];
        bool     hashed = (L.hashed[l] != 0);

        float pxa = fmaf(gx0, scale, 0.5f);
        float pxb = fmaf(gx1, scale, 0.5f);
        float pya = fmaf(gyA, scale, 0.5f);
        float pyb = fmaf(gyB, scale, 0.5f);
        float fxa = floorf(pxa), fxb = floorf(pxb);
        float fya = floorf(pya), fyb = floorf(pyb);
        float ua1 = pxa - fxa, ua0 = 1.0f - ua1;
        float ub1 = pxb - fxb, ub0 = 1.0f - ub1;
        float va1 = pya - fya, va0 = 1.0f - va1;
        float vb1 = pyb - fyb, vb0 = 1.0f - vb1;
        unsigned ix = (unsigned)fxa, iy = (unsigned)fya;
        bool bdx = fxb > fxa;     // corners straddle a cell in x
        bool bdy = fyb > fya;

        // 3x3 union of the 4 corners' bilinear taps
        unsigned i00, i01, i02, i10, i11, i12, i20, i21, i22;
        if (hashed) {
            unsigned m = size - 1u;
            unsigned hy0 = iy * PRIME_Y, hy1 = hy0 + PRIME_Y, hy2 = hy1 + PRIME_Y;
            i00 = (ix ^ hy0) & m; i01 = ((ix + 1u) ^ hy0) & m; i02 = ((ix + 2u) ^ hy0) & m;
            i10 = (ix ^ hy1) & m; i11 = ((ix + 1u) ^ hy1) & m; i12 = ((ix + 2u) ^ hy1) & m;
            i20 = (ix ^ hy2) & m; i21 = ((ix + 1u) ^ hy2) & m; i22 = ((ix + 2u) ^ hy2) & m;
        } else {
            unsigned hy0 = iy * res, hy1 = hy0 + res, hy2 = hy1 + res;
            i00 = ix + hy0;      if (i00 >= size) i00 -= size;
            i01 = ix + 1u + hy0; if (i01 >= size) i01 -= size;
            i02 = ix + 2u + hy0; if (i02 >= size) i02 -= size;
            i10 = ix + hy1;      if (i10 >= size) i10 -= size;
            i11 = ix + 1u + hy1; if (i11 >= size) i11 -= size;
            i12 = ix + 2u + hy1; if (i12 >= size) i12 -= size;
            i20 = ix + hy2;      if (i20 >= size) i20 -= size;
            i21 = ix + 1u + hy2; if (i21 >= size) i21 -= size;
            i22 = ix + 2u + hy2; if (i22 >= size) i22 -= size;
        }

        const u64* tb = (const u64*)(table + off);
        u64 T00 = __ldg(tb + i00);
        u64 T01 = __ldg(tb + i01);
        u64 T10 = __ldg(tb + i10);
        u64 T11 = __ldg(tb + i11);
        u64 T02 = 0ull, T12 = 0ull, T20 = 0ull, T21 = 0ull, T22 = 0ull;
        if (bdx) { T02 = __ldg(tb + i02); T12 = __ldg(tb + i12); }
        if (bdy) { T20 = __ldg(tb + i20); T21 = __ldg(tb + i21); }
        if (bdx && bdy) { T22 = __ldg(tb + i22); }

        u64 ua0p = pk2(ua0, ua0), ua1p = pk2(ua1, ua1);
        u64 ub0p = pk2(ub0, ub0), ub1p = pk2(ub1, ub1);
        u64 va0p = pk2(va0, va0), va1p = pk2(va1, va1);
        u64 vb0p = pk2(vb0, vb0), vb1p = pk2(vb1, vb1);

        u64 S00 = ffma2(ua1p, T01, mul2(ua0p, T00));
        u64 S01 = ffma2(ua1p, T11, mul2(ua0p, T10));
        u64 S02 = ffma2(ua1p, T21, mul2(ua0p, T20));
        u64 X0r0 = bdx ? T01 : T00, X1r0 = bdx ? T02 : T01;
        u64 X0r1 = bdx ? T11 : T10, X1r1 = bdx ? T12 : T11;
        u64 X0r2 = bdx ? T21 : T20, X1r2 = bdx ? T22 : T21;
        u64 S10 = ffma2(ub1p, X1r0, mul2(ub0p, X0r0));
        u64 S11 = ffma2(ub1p, X1r1, mul2(ub0p, X0r1));
        u64 S12 = ffma2(ub1p, X1r2, mul2(ub0p, X0r2));

        Fa[l] = ffma2(va1p, S01, mul2(va0p, S00));
        Fb[l] = ffma2(va1p, S11, mul2(va0p, S10));
        u64 Y0a = bdy ? S01 : S00, Y1a = bdy ? S02 : S01;
        u64 Y0b = bdy ? S11 : S10, Y1b = bdy ? S12 : S11;
        mFc[l] = ffma2(vb1p, Y1a, mul2(vb0p, Y0a));
        mFd[l] = ffma2(vb1p, Y1b, mul2(vb0p, Y0b));
    }

    float cwa = (1.0f - u) * (1.0f - v);
    float cwb = u * (1.0f - v);
    float cwc = (1.0f - u) * v;
    float cwd = u * v;

    // Fused MLP: layer1 (per-corner relu, bilinear blend) folded straight into
    // layer2 accumulators. Weights from the constant port; Fc/Fd via LDS.128.
    u64 O0 = 0ull, O1 = 0ull, O2 = 0ull, O3 = 0ull;
    #pragma unroll 1
    for (int j2 = 0; j2 < 32; j2++) {
        const ulonglong2* r0 = (const ulonglong2*)&cW0[(2 * j2) * 32];
        const ulonglong2* r1 = (const ulonglong2*)&cW0[(2 * j2 + 1) * 32];
        u64 a0 = 0ull, b0 = 0ull, c0 = 0ull, d0 = 0ull;
        u64 a1 = 0ull, b1 = 0ull, c1 = 0ull, d1 = 0ull;
        #pragma unroll
        for (int i = 0; i < 8; i++) {
            ulonglong2 w_0 = r0[i], w_1 = r1[i];
            ulonglong2 fc = *(const ulonglong2*)&mFc[2 * i];
            ulonglong2 fd = *(const ulonglong2*)&mFd[2 * i];
            a0 = ffma2(Fa[2 * i], w_0.x, a0); a0 = ffma2(Fa[2 * i + 1], w_0.y, a0);
            b0 = ffma2(Fb[2 * i], w_0.x, b0); b0 = ffma2(Fb[2 * i + 1], w_0.y, b0);
            c0 = ffma2(fc.x,      w_0.x, c0); c0 = ffma2(fc.y,          w_0.y, c0);
            d0 = ffma2(fd.x,      w_0.x, d0); d0 = ffma2(fd.y,          w_0.y, d0);
            a1 = ffma2(Fa[2 * i], w_1.x, a1); a1 = ffma2(Fa[2 * i + 1], w_1.y, a1);
            b1 = ffma2(Fb[2 * i], w_1.x, b1); b1 = ffma2(Fb[2 * i + 1], w_1.y, b1);
            c1 = ffma2(fc.x,      w_1.x, c1); c1 = ffma2(fc.y,          w_1.y, c1);
            d1 = ffma2(fd.x,      w_1.x, d1); d1 = ffma2(fd.y,          w_1.y, d1);
        }
        float2 A0 = upk2(a0), B0 = upk2(b0), C0 = upk2(c0), D0 = upk2(d0);
        float2 A1 = upk2(a1), B1 = upk2(b1), C1 = upk2(c1), D1 = upk2(d1);
        float h0 = fmaxf(A0.x + A0.y, 0.0f) * cwa;
        h0 = fmaf(fmaxf(B0.x + B0.y, 0.0f), cwb, h0);
        h0 = fmaf(fmaxf(C0.x + C0.y, 0.0f), cwc, h0);
        h0 = fmaf(fmaxf(D0.x + D0.y, 0.0f), cwd, h0);
        float h1 = fmaxf(A1.x + A1.y, 0.0f) * cwa;
        h1 = fmaf(fmaxf(B1.x + B1.y, 0.0f), cwb, h1);
        h1 = fmaf(fmaxf(C1.x + C1.y, 0.0f), cwc, h1);
        h1 = fmaf(fmaxf(D1.x + D1.y, 0.0f), cwd, h1);

        const ulonglong2* wt = (const ulonglong2*)&cW1t[(2 * j2) * 8];
        ulonglong2 q0 = wt[0], q1 = wt[1];   // row 2j2:   k 0..3, 4..7
        ulonglong2 q2 = wt[2], q3 = wt[3];   // row 2j2+1
        u64 t0 = pk2(h0, h0), t1 = pk2(h1, h1);
        O0 = ffma2(t0, q0.x, O0); O1 = ffma2(t0, q0.y, O1);
        O2 = ffma2(t0, q1.x, O2); O3 = ffma2(t0, q1.y, O3);
        O0 = ffma2(t1, q2.x, O0); O1 = ffma2(t1, q2.y, O1);
        O2 = ffma2(t1, q3.x, O2); O3 = ffma2(t1, q3.y, O3);
    }

    float2 r0 = upk2(O0), r1 = upk2(O1), r2 = upk2(O2), r3 = upk2(O3);
    float4* op = (float4*)(out + (size_t)n * 8);
    op[0] = make_float4(r0.x, r0.y, r1.x, r1.y);
    op[1] = make_float4(r2.x, r2.y, r3.x, r3.y);
}

extern "C" void kernel_launch(void* const* d_in, const int* in_sizes, int n_in,
                              void* d_out, int out_size)
{
    const float2* xy    = (const float2*)d_in[0];
    const float2* table = (const float2*)d_in[1];
    const float*  w0    = (const float*)d_in[2];
    const float*  w1    = (const float*)d_in[3];
    const unsigned* bound = (n_in > 4) ? (const unsigned*)d_in[4] : nullptr;
    int bound_elems = (n_in > 4) ? in_sizes[4] : 0;

    int N = in_sizes[0] / 2;

    cudaMemcpyToSymbolAsync(cW0, w0, 64 * 32 * sizeof(float), 0,
                            cudaMemcpyDeviceToDevice, 0);
    // Transpose w1 on device, then stage into constant memory.
    transpose_w1<<<1, 512>>>(w1);
    void* w1t_ptr = nullptr;
    cudaGetSymbolAddress(&w1t_ptr, g_w1t);
    cudaMemcpyToSymbolAsync(cW1t, w1t_ptr, 64 * 8 * sizeof(float), 0,
                            cudaMemcpyDeviceToDevice, 0);

    // Level constants — same double-precision libm sequence as the numpy
    // reference so ceil() boundaries match exactly.
    Levels L;
    double b = exp2(log2(2048.0 / 16.0) / 15.0);
    unsigned off = 0;
    for (int l = 0; l < NLEV; l++) {
        double s = 16.0 * pow(b, (double)l) - 1.0;
        int r = (int)ceil(s) + 1;
        unsigned long long pp = (unsigned long long)r * (unsigned long long)r;
        unsigned psz = (pp > (unsigned long long)(1u << 19)) ? (1u << 19) : (unsigned)pp;
        psz = (psz + 7u) / 8u * 8u;
        L.scale[l]  = (float)s;
        L.res[l]    = (unsigned)r;
        L.size[l]   = psz;
        L.offset[l] = off;
        L.hashed[l] = (pp > (unsigned long long)psz) ? 1u : 0u;
        off += psz;
    }

    int threads = 128;
    int blocks = (N + threads - 1) / threads;
    plane_kernel<<<blocks, threads>>>(xy, table, bound, bound_elems,
                                      (float*)d_out, N, L);
}

// round 11
// speedup vs baseline: 2.1156x; 2.1156x over previous
#include <cuda_runtime.h>
#include <cuda_fp16.h>
#include <math.h>

#define NLEV 16
#define RESO 2048
#define PRIME_Y 2654435761u
#define FSCALE 4096.0f
#define INV_FSCALE (1.0f / 4096.0f)

#define A_STRIDE_H 40   // halves per A row: banks (20g+tig)%32 distinct -> conflict-free
#define W_STRIDE_H 40   // halves per W0 row: banks (20n+tig)%32 distinct -> conflict-free
#define H_STRIDE 68     // floats per h row (64 + 4 pad), 16B-aligned rows

struct Levels {
    float    scale[NLEV];
    unsigned res[NLEV];
    unsigned size[NLEV];
    unsigned offset[NLEV];
    unsigned hashed[NLEV];
};

typedef unsigned long long u64;
typedef unsigned int u32;

__constant__ float cW1[8 * 64];   // layer-2 weights, fp32, [k][j] row-major

__device__ __forceinline__ u64 pk2(float lo, float hi) {
    u64 r; asm("mov.b64 %0,{%1,%2};" : "=l"(r) : "f"(lo), "f"(hi)); return r;
}
__device__ __forceinline__ float2 upk2(u64 a) {
    float2 f; asm("mov.b64 {%0,%1},%2;" : "=f"(f.x), "=f"(f.y) : "l"(a)); return f;
}
__device__ __forceinline__ u64 ffma2(u64 a, u64 b, u64 c) {
    u64 d; asm("fma.rn.f32x2 %0,%1,%2,%3;" : "=l"(d) : "l"(a), "l"(b), "l"(c)); return d;
}
__device__ __forceinline__ u64 mul2(u64 a, u64 b) {
    u64 d; asm("mul.rn.f32x2 %0,%1,%2;" : "=l"(d) : "l"(a), "l"(b)); return d;
}
__device__ __forceinline__ u32 cvt_h2(u64 pair) {
    float2 f = upk2(pair);
    __half2 hv = __floats2half2_rn(f.x, f.y);   // low half = f.x (even feature)
    return *reinterpret_cast<u32*>(&hv);
}

__device__ __forceinline__ float decode_bound(const unsigned* p, int elems) {
    if (!p || elems <= 0) return 1.0f;
    unsigned a = p[0];
    float ff = __uint_as_float(a);
    if (isfinite(ff) && fabsf(ff) > 1e-6f && fabsf(ff) < 1e9f) return ff;
    int ai = (int)a;
    if (ai != 0 && ai > -1000000000 && ai < 1000000000) return (float)ai;
    if (elems >= 2) {
        double d = __hiloint2double((int)p[1], (int)a);
        if (isfinite(d) && fabs(d) > 1e-6 && fabs(d) < 1e9) return (float)d;
    }
    return 1.0f;
}

__global__ __launch_bounds__(128)
void plane_kernel(const float2* __restrict__ xy,
                  const float2* __restrict__ table,
                  const float*  __restrict__ w0g,
                  const unsigned* __restrict__ bound_raw,
                  int bound_elems,
                  float* __restrict__ out,
                  int N, Levels L)
{
    // Per-warp A staging (fp16 features, 128 rows x 40 halves); reused as the
    // h-transpose buffer (32 rows x 68 floats) after the MMAs.
    __shared__ __align__(16) __half sA[4][128 * A_STRIDE_H];
    __shared__ __align__(16) __half sW0h[64 * W_STRIDE_H];

    const int tid = threadIdx.x;
    const int wid = tid >> 5;
    const int lid = tid & 31;
    const int g   = lid >> 2;   // groupID
    const int tig = lid & 3;    // threadID_in_group

    for (int i = tid; i < 64 * 32; i += 128) {
        int j = i >> 5, k = i & 31;
        sW0h[j * W_STRIDE_H + k] = __float2half(w0g[i]);
    }
    __syncthreads();

    int n = blockIdx.x * 128 + tid;
    bool active = (n < N);
    int nc = active ? n : (N - 1);

    float bound = decode_bound(bound_raw, bound_elems);

    float2 p = xy[nc];
    float inv2b = 0.5f / bound;
    float nxv = (p.x + bound) * inv2b;
    float nyv = (p.y + bound) * inv2b;
    float cxf = fminf(fmaxf(nxv * (float)RESO - 0.5f, 0.0f), (float)(RESO - 1));
    float cyf = fminf(fmaxf(nyv * (float)RESO - 0.5f, 0.0f), (float)(RESO - 1));
    float cx0 = floorf(cxf), cy0 = floorf(cyf);
    float cx1 = fminf(cx0 + 1.0f, (float)(RESO - 1));
    float cy1 = fminf(cy0 + 1.0f, (float)(RESO - 1));
    float u = cxf - cx0, v = cyf - cy0;

    float gx0 = (cx0 + 0.5f) * (1.0f / (float)RESO);
    float gx1 = (cx1 + 0.5f) * (1.0f / (float)RESO);
    float gyA = (cy0 + 0.5f) * (1.0f / (float)RESO);
    float gyB = (cy1 + 0.5f) * (1.0f / (float)RESO);

    // fp16 feature rows (x FSCALE), one half2 per level per corner.
    u32 Ha[NLEV], Hb[NLEV], Hc[NLEV], Hd[NLEV];

    #pragma unroll
    for (int l = 0; l < NLEV; l++) {
        float    scale  = L.scale[l];
        unsigned res    = L.res[l];
        unsigned size   = L.size[l];
        unsigned off    = L.offset[l];
        bool     hashed = (L.hashed[l] != 0);

        float pxa = fmaf(gx0, scale, 0.5f);
        float pxb = fmaf(gx1, scale, 0.5f);
        float pya = fmaf(gyA, scale, 0.5f);
        float pyb = fmaf(gyB, scale, 0.5f);
        float fxa = floorf(pxa), fxb = floorf(pxb);
        float fya = floorf(pya), fyb = floorf(pyb);
        float ua1 = pxa - fxa, ua0 = 1.0f - ua1;
        float ub1 = pxb - fxb, ub0 = 1.0f - ub1;
        float va1 = (pya - fya) * FSCALE, va0 = FSCALE - va1;
        float vb1 = (pyb - fyb) * FSCALE, vb0 = FSCALE - vb1;
        unsigned ix = (unsigned)fxa, iy = (unsigned)fya;
        bool bdx = fxb > fxa;
        bool bdy = fyb > fya;

        unsigned i00, i01, i02, i10, i11, i12, i20, i21, i22;
        if (hashed) {
            unsigned m = size - 1u;
            unsigned hy0 = iy * PRIME_Y, hy1 = hy0 + PRIME_Y, hy2 = hy1 + PRIME_Y;
            i00 = (ix ^ hy0) & m; i01 = ((ix + 1u) ^ hy0) & m; i02 = ((ix + 2u) ^ hy0) & m;
            i10 = (ix ^ hy1) & m; i11 = ((ix + 1u) ^ hy1) & m; i12 = ((ix + 2u) ^ hy1) & m;
            i20 = (ix ^ hy2) & m; i21 = ((ix + 1u) ^ hy2) & m; i22 = ((ix + 2u) ^ hy2) & m;
        } else {
            unsigned hy0 = iy * res, hy1 = hy0 + res, hy2 = hy1 + res;
            i00 = ix + hy0;      if (i00 >= size) i00 -= size;
            i01 = ix + 1u + hy0; if (i01 >= size) i01 -= size;
            i02 = ix + 2u + hy0; if (i02 >= size) i02 -= size;
            i10 = ix + hy1;      if (i10 >= size) i10 -= size;
            i11 = ix + 1u + hy1; if (i11 >= size) i11 -= size;
            i12 = ix + 2u + hy1; if (i12 >= size) i12 -= size;
            i20 = ix + hy2;      if (i20 >= size) i20 -= size;
            i21 = ix + 1u + hy2; if (i21 >= size) i21 -= size;
            i22 = ix + 2u + hy2; if (i22 >= size) i22 -= size;
        }

        const u64* tb = (const u64*)(table + off);
        u64 T00 = __ldg(tb + i00);
        u64 T01 = __ldg(tb + i01);
        u64 T10 = __ldg(tb + i10);
        u64 T11 = __ldg(tb + i11);
        u64 T02 = 0ull, T12 = 0ull, T20 = 0ull, T21 = 0ull, T22 = 0ull;
        if (bdx) { T02 = __ldg(tb + i02); T12 = __ldg(tb + i12); }
        if (bdy) { T20 = __ldg(tb + i20); T21 = __ldg(tb + i21); }
        if (bdx && bdy) { T22 = __ldg(tb + i22); }

        u64 ua0p = pk2(ua0, ua0), ua1p = pk2(ua1, ua1);
        u64 ub0p = pk2(ub0, ub0), ub1p = pk2(ub1, ub1);
        u64 va0p = pk2(va0, va0), va1p = pk2(va1, va1);
        u64 vb0p = pk2(vb0, vb0), vb1p = pk2(vb1, vb1);

        u64 S00 = ffma2(ua1p, T01, mul2(ua0p, T00));
        u64 S01 = ffma2(ua1p, T11, mul2(ua0p, T10));
        u64 S02 = ffma2(ua1p, T21, mul2(ua0p, T20));
        u64 X0r0 = bdx ? T01 : T00, X1r0 = bdx ? T02 : T01;
        u64 X0r1 = bdx ? T11 : T10, X1r1 = bdx ? T12 : T11;
        u64 X0r2 = bdx ? T21 : T20, X1r2 = bdx ? T22 : T21;
        u64 S10 = ffma2(ub1p, X1r0, mul2(ub0p, X0r0));
        u64 S11 = ffma2(ub1p, X1r1, mul2(ub0p, X0r1));
        u64 S12 = ffma2(ub1p, X1r2, mul2(ub0p, X0r2));

        Ha[l] = cvt_h2(ffma2(va1p, S01, mul2(va0p, S00)));
        Hb[l] = cvt_h2(ffma2(va1p, S11, mul2(va0p, S10)));
        u64 Y0a = bdy ? S01 : S00, Y1a = bdy ? S02 : S01;
        u64 Y0b = bdy ? S11 : S10, Y1b = bdy ? S12 : S11;
        Hc[l] = cvt_h2(ffma2(vb1p, Y1a, mul2(vb0p, Y0a)));
        Hd[l] = cvt_h2(ffma2(vb1p, Y1b, mul2(vb0p, Y0b)));
    }

    // Stage A rows: row (corner*32 + lane) = fp16 features of this thread's
    // point at that corner.
    __half* myA = sA[wid];
    {
        uint4* r0 = (uint4*)(myA + (0 * 32 + lid) * A_STRIDE_H);
        r0[0] = make_uint4(Ha[0], Ha[1], Ha[2], Ha[3]);
        r0[1] = make_uint4(Ha[4], Ha[5], Ha[6], Ha[7]);
        r0[2] = make_uint4(Ha[8], Ha[9], Ha[10], Ha[11]);
        r0[3] = make_uint4(Ha[12], Ha[13], Ha[14], Ha[15]);
        uint4* r1 = (uint4*)(myA + (1 * 32 + lid) * A_STRIDE_H);
        r1[0] = make_uint4(Hb[0], Hb[1], Hb[2], Hb[3]);
        r1[1] = make_uint4(Hb[4], Hb[5], Hb[6], Hb[7]);
        r1[2] = make_uint4(Hb[8], Hb[9], Hb[10], Hb[11]);
        r1[3] = make_uint4(Hb[12], Hb[13], Hb[14], Hb[15]);
        uint4* r2 = (uint4*)(myA + (2 * 32 + lid) * A_STRIDE_H);
        r2[0] = make_uint4(Hc[0], Hc[1], Hc[2], Hc[3]);
        r2[1] = make_uint4(Hc[4], Hc[5], Hc[6], Hc[7]);
        r2[2] = make_uint4(Hc[8], Hc[9], Hc[10], Hc[11]);
        r2[3] = make_uint4(Hc[12], Hc[13], Hc[14], Hc[15]);
        uint4* r3 = (uint4*)(myA + (3 * 32 + lid) * A_STRIDE_H);
        r3[0] = make_uint4(Hd[0], Hd[1], Hd[2], Hd[3]);
        r3[1] = make_uint4(Hd[4], Hd[5], Hd[6], Hd[7]);
        r3[2] = make_uint4(Hd[8], Hd[9], Hd[10], Hd[11]);
        r3[3] = make_uint4(Hd[12], Hd[13], Hd[14], Hd[15]);
    }
    __syncwarp();

    // B fragments (per mma spec): n = nt*8 + g; b0 = w0[n][kc*16+2tig..+1],
    // b1 = +8 columns. Conflict-free with W_STRIDE_H=40.
    u32 Bf[2][8][2];
    #pragma unroll
    for (int kc = 0; kc < 2; kc++) {
        #pragma unroll
        for (int nt = 0; nt < 8; nt++) {
            const u32* wrow = (const u32*)&sW0h[(nt * 8 + g) * W_STRIDE_H + kc * 16];
            Bf[kc][nt][0] = wrow[tig];
            Bf[kc][nt][1] = wrow[tig + 4];
        }
    }

    float cw[4];
    cw[0] = (1.0f - u) * (1.0f - v) * INV_FSCALE;
    cw[1] = u * (1.0f - v) * INV_FSCALE;
    cw[2] = (1.0f - u) * v * INV_FSCALE;
    cw[3] = u * v * INV_FSCALE;

    // Blended hidden activations, D-fragment layout: [mtp][nt][4].
    float hb[2][8][4];
    #pragma unroll
    for (int a = 0; a < 2; a++)
        #pragma unroll
        for (int b = 0; b < 8; b++)
            #pragma unroll
            for (int c = 0; c < 4; c++) hb[a][b][c] = 0.0f;

    #pragma unroll
    for (int c = 0; c < 4; c++) {
        #pragma unroll
        for (int mtp = 0; mtp < 2; mtp++) {
            // THE FIX: D-fragment rows g / g+8 belong to points (mtp*16+g) and
            // (mtp*16+g+8), NOT to this thread's point. Fetch those points'
            // blend weights for corner c via shfl.
            float wlo = __shfl_sync(0xffffffffu, cw[c], mtp * 16 + g);
            float whi = __shfl_sync(0xffffffffu, cw[c], mtp * 16 + g + 8);

            u32 afr[2][4];
            #pragma unroll
            for (int kc = 0; kc < 2; kc++) {
                const __half* ar =
                    myA + (c * 32 + mtp * 16 + g) * A_STRIDE_H + kc * 16 + tig * 2;
                afr[kc][0] = *(const u32*)(ar);
                afr[kc][1] = *(const u32*)(ar + 8 * A_STRIDE_H);
                afr[kc][2] = *(const u32*)(ar + 8);
                afr[kc][3] = *(const u32*)(ar + 8 * A_STRIDE_H + 8);
            }
            #pragma unroll
            for (int nt = 0; nt < 8; nt++) {
                float d0 = 0.0f, d1 = 0.0f, d2 = 0.0f, d3 = 0.0f;
                asm volatile("mma.sync.aligned.m16n8k16.row.col.f32.f16.f16.f32 "
                    "{%0,%1,%2,%3},{%4,%5,%6,%7},{%8,%9},{%0,%1,%2,%3};"
                    : "+f"(d0), "+f"(d1), "+f"(d2), "+f"(d3)
                    : "r"(afr[0][0]), "r"(afr[0][1]), "r"(afr[0][2]), "r"(afr[0][3]),
                      "r"(Bf[0][nt][0]), "r"(Bf[0][nt][1]));
                asm volatile("mma.sync.aligned.m16n8k16.row.col.f32.f16.f16.f32 "
                    "{%0,%1,%2,%3},{%4,%5,%6,%7},{%8,%9},{%0,%1,%2,%3};"
                    : "+f"(d0), "+f"(d1), "+f"(d2), "+f"(d3)
                    : "r"(afr[1][0]), "r"(afr[1][1]), "r"(afr[1][2]), "r"(afr[1][3]),
                      "r"(Bf[1][nt][0]), "r"(Bf[1][nt][1]));
                hb[mtp][nt][0] = fmaf(fmaxf(d0, 0.0f), wlo, hb[mtp][nt][0]);
                hb[mtp][nt][1] = fmaf(fmaxf(d1, 0.0f), wlo, hb[mtp][nt][1]);
                hb[mtp][nt][2] = fmaf(fmaxf(d2, 0.0f), whi, hb[mtp][nt][2]);
                hb[mtp][nt][3] = fmaf(fmaxf(d3, 0.0f), whi, hb[mtp][nt][3]);
            }
        }
    }
    __syncwarp();

    // Transpose h to per-point rows (reuse A region): point mtp*16+g(+8),
    // columns 8*nt + 2*tig (+1).
    float* hT = (float*)myA;
    {
        #pragma unroll
        for (int mtp = 0; mtp < 2; mtp++) {
            #pragma unroll
            for (int nt = 0; nt < 8; nt++) {
                int colw = 8 * nt + 2 * tig;
                *(float2*)&hT[(g + 16 * mtp) * H_STRIDE + colw] =
                    make_float2(hb[mtp][nt][0], hb[mtp][nt][1]);
                *(float2*)&hT[(g + 8 + 16 * mtp) * H_STRIDE + colw] =
                    make_float2(hb[mtp][nt][2], hb[mtp][nt][3]);
            }
        }
    }
    __syncwarp();

    // Layer 2 (fp32, constant port) on this thread's point.
    u64 HB[32];
    {
        const float4* hrow = (const float4*)&hT[lid * H_STRIDE];
        #pragma unroll
        for (int m = 0; m < 16; m++) {
            float4 q = hrow[m];
            HB[2 * m]     = pk2(q.x, q.y);
            HB[2 * m + 1] = pk2(q.z, q.w);
        }
    }

    float ov[8];
    #pragma unroll
    for (int k = 0; k < 8; k++) {
        const ulonglong2* wr = (const ulonglong2*)&cW1[k * 64];
        u64 a0 = 0ull, a1 = 0ull;
        #pragma unroll
        for (int m = 0; m < 16; m++) {
            ulonglong2 w2 = wr[m];
            a0 = ffma2(HB[2 * m],     w2.x, a0);
            a1 = ffma2(HB[2 * m + 1], w2.y, a1);
        }
        float2 s0 = upk2(a0), s1 = upk2(a1);
        ov[k] = (s0.x + s0.y) + (s1.x + s1.y);
    }

    if (active) {
        float4* op = (float4*)(out + (size_t)n * 8);
        op[0] = make_float4(ov[0], ov[1], ov[2], ov[3]);
        op[1] = make_float4(ov[4], ov[5], ov[6], ov[7]);
    }
}

extern "C" void kernel_launch(void* const* d_in, const int* in_sizes, int n_in,
                              void* d_out, int out_size)
{
    const float2* xy    = (const float2*)d_in[0];
    const float2* table = (const float2*)d_in[1];
    const float*  w0    = (const float*)d_in[2];
    const float*  w1    = (const float*)d_in[3];
    const unsigned* bound = (n_in > 4) ? (const unsigned*)d_in[4] : nullptr;
    int bound_elems = (n_in > 4) ? in_sizes[4] : 0;

    int N = in_sizes[0] / 2;

    cudaMemcpyToSymbolAsync(cW1, w1, 8 * 64 * sizeof(float), 0,
                            cudaMemcpyDeviceToDevice, 0);

    // Level constants — same double-precision libm sequence as the numpy
    // reference so ceil() boundaries match exactly.
    Levels L;
    double b = exp2(log2(2048.0 / 16.0) / 15.0);
    unsigned off = 0;
    for (int l = 0; l < NLEV; l++) {
        double s = 16.0 * pow(b, (double)l) - 1.0;
        int r = (int)ceil(s) + 1;
        unsigned long long pp = (unsigned long long)r * (unsigned long long)r;
        unsigned psz = (pp > (unsigned long long)(1u << 19)) ? (1u << 19) : (unsigned)pp;
        psz = (psz + 7u) / 8u * 8u;
        L.scale[l]  = (float)s;
        L.res[l]    = (unsigned)r;
        L.size[l]   = psz;
        L.offset[l] = off;
        L.hashed[l] = (pp > (unsigned long long)psz) ? 1u : 0u;
        off += psz;
    }

    int blocks = (N + 127) / 128;
    plane_kernel<<<blocks, 128>>>(xy, table, w0, bound, bound_elems,
                                  (float*)d_out, N, L);
}

// round 12
// speedup vs baseline: 2.4287x; 1.1480x over previous
#include <cuda_runtime.h>
#include <cuda_fp16.h>
#include <math.h>

#define NLEV 16
#define RESO 2048
#define PRIME_Y 2654435761u
#define FSCALE 4096.0f
#define INV_FSCALE (1.0f / 4096.0f)

#define A_STRIDE_H 40   // halves per A row: banks (20g+tig)%32 distinct -> conflict-free
#define W_STRIDE_H 40   // halves per W0 row: same property

struct Levels {
    float    scale[NLEV];
    unsigned res[NLEV];
    unsigned size[NLEV];
    unsigned offset[NLEV];
    unsigned hashed[NLEV];
};

typedef unsigned long long u64;
typedef unsigned int u32;

__device__ __forceinline__ u64 pk2(float lo, float hi) {
    u64 r; asm("mov.b64 %0,{%1,%2};" : "=l"(r) : "f"(lo), "f"(hi)); return r;
}
__device__ __forceinline__ float2 upk2(u64 a) {
    float2 f; asm("mov.b64 {%0,%1},%2;" : "=f"(f.x), "=f"(f.y) : "l"(a)); return f;
}
__device__ __forceinline__ u64 ffma2(u64 a, u64 b, u64 c) {
    u64 d; asm("fma.rn.f32x2 %0,%1,%2,%3;" : "=l"(d) : "l"(a), "l"(b), "l"(c)); return d;
}
__device__ __forceinline__ u64 mul2(u64 a, u64 b) {
    u64 d; asm("mul.rn.f32x2 %0,%1,%2;" : "=l"(d) : "l"(a), "l"(b)); return d;
}
__device__ __forceinline__ u32 cvt_h2(u64 pair) {
    float2 f = upk2(pair);
    __half2 hv = __floats2half2_rn(f.x, f.y);   // low half = f.x
    return *reinterpret_cast<u32*>(&hv);
}
__device__ __forceinline__ u32 cvt_h2f(float lo, float hi) {
    __half2 hv = __floats2half2_rn(lo, hi);
    return *reinterpret_cast<u32*>(&hv);
}

__device__ __forceinline__ float decode_bound(const unsigned* p, int elems) {
    if (!p || elems <= 0) return 1.0f;
    unsigned a = p[0];
    float ff = __uint_as_float(a);
    if (isfinite(ff) && fabsf(ff) > 1e-6f && fabsf(ff) < 1e9f) return ff;
    int ai = (int)a;
    if (ai != 0 && ai > -1000000000 && ai < 1000000000) return (float)ai;
    if (elems >= 2) {
        double d = __hiloint2double((int)p[1], (int)a);
        if (isfinite(d) && fabs(d) > 1e-6 && fabs(d) < 1e9) return (float)d;
    }
    return 1.0f;
}

__global__ __launch_bounds__(128, 4)
void plane_kernel(const float2* __restrict__ xy,
                  const float2* __restrict__ table,
                  const float*  __restrict__ w0g,
                  const float*  __restrict__ w1g,
                  const unsigned* __restrict__ bound_raw,
                  int bound_elems,
                  float* __restrict__ out,
                  int N, Levels L)
{
    __shared__ __align__(16) __half sA[4][128 * A_STRIDE_H];  // per-warp A staging
    __shared__ __align__(16) __half sW0h[64 * W_STRIDE_H];    // W0 fp16 [j][i]
    __shared__ __align__(16) __half sW1h[8 * 64];             // W1 fp16 [k][j]

    const int tid = threadIdx.x;
    const int wid = tid >> 5;
    const int lid = tid & 31;
    const int g   = lid >> 2;   // groupID
    const int tig = lid & 3;    // threadID_in_group

    for (int i = tid; i < 64 * 32; i += 128) {
        int j = i >> 5, k = i & 31;
        sW0h[j * W_STRIDE_H + k] = __float2half(w0g[i]);
    }
    for (int i = tid; i < 8 * 64; i += 128) sW1h[i] = __float2half(w1g[i]);
    __syncthreads();

    int n = blockIdx.x * 128 + tid;
    int nc = (n < N) ? n : (N - 1);

    float bound = decode_bound(bound_raw, bound_elems);

    float2 p = xy[nc];
    float inv2b = 0.5f / bound;
    float nxv = (p.x + bound) * inv2b;
    float nyv = (p.y + bound) * inv2b;
    float cxf = fminf(fmaxf(nxv * (float)RESO - 0.5f, 0.0f), (float)(RESO - 1));
    float cyf = fminf(fmaxf(nyv * (float)RESO - 0.5f, 0.0f), (float)(RESO - 1));
    float cx0 = floorf(cxf), cy0 = floorf(cyf);
    float cx1 = fminf(cx0 + 1.0f, (float)(RESO - 1));
    float cy1 = fminf(cy0 + 1.0f, (float)(RESO - 1));
    float u = cxf - cx0, v = cyf - cy0;

    float gx0 = (cx0 + 0.5f) * (1.0f / (float)RESO);
    float gx1 = (cx1 + 0.5f) * (1.0f / (float)RESO);
    float gyA = (cy0 + 0.5f) * (1.0f / (float)RESO);
    float gyB = (cy1 + 0.5f) * (1.0f / (float)RESO);

    __half* myA = sA[wid];

    // Encode in 4-level groups; stage each group's uint4 immediately so only
    // 16 packed feature regs are live (vs 64 before).
    #pragma unroll
    for (int lg = 0; lg < 4; lg++) {
        u32 Pa[4], Pb[4], Pc[4], Pd[4];
        #pragma unroll
        for (int li = 0; li < 4; li++) {
            const int l = lg * 4 + li;
            float    scale  = L.scale[l];
            unsigned res    = L.res[l];
            unsigned size   = L.size[l];
            unsigned off    = L.offset[l];
            bool     hashed = (L.hashed[l] != 0);

            float pxa = fmaf(gx0, scale, 0.5f);
            float pxb = fmaf(gx1, scale, 0.5f);
            float pya = fmaf(gyA, scale, 0.5f);
            float pyb = fmaf(gyB, scale, 0.5f);
            float fxa = floorf(pxa), fxb = floorf(pxb);
            float fya = floorf(pya), fyb = floorf(pyb);
            float ua1 = pxa - fxa, ua0 = 1.0f - ua1;
            float ub1 = pxb - fxb, ub0 = 1.0f - ub1;
            float va1 = (pya - fya) * FSCALE, va0 = FSCALE - va1;
            float vb1 = (pyb - fyb) * FSCALE, vb0 = FSCALE - vb1;
            unsigned ix = (unsigned)fxa, iy = (unsigned)fya;
            bool bdx = fxb > fxa;
            bool bdy = fyb > fya;

            unsigned i00, i01, i02, i10, i11, i12, i20, i21, i22;
            if (hashed) {
                unsigned m = size - 1u;
                unsigned hy0 = iy * PRIME_Y, hy1 = hy0 + PRIME_Y, hy2 = hy1 + PRIME_Y;
                i00 = (ix ^ hy0) & m; i01 = ((ix + 1u) ^ hy0) & m; i02 = ((ix + 2u) ^ hy0) & m;
                i10 = (ix ^ hy1) & m; i11 = ((ix + 1u) ^ hy1) & m; i12 = ((ix + 2u) ^ hy1) & m;
                i20 = (ix ^ hy2) & m; i21 = ((ix + 1u) ^ hy2) & m; i22 = ((ix + 2u) ^ hy2) & m;
            } else {
                unsigned hy0 = iy * res, hy1 = hy0 + res, hy2 = hy1 + res;
                i00 = ix + hy0;      if (i00 >= size) i00 -= size;
                i01 = ix + 1u + hy0; if (i01 >= size) i01 -= size;
                i02 = ix + 2u + hy0; if (i02 >= size) i02 -= size;
                i10 = ix + hy1;      if (i10 >= size) i10 -= size;
                i11 = ix + 1u + hy1; if (i11 >= size) i11 -= size;
                i12 = ix + 2u + hy1; if (i12 >= size) i12 -= size;
                i20 = ix + hy2;      if (i20 >= size) i20 -= size;
                i21 = ix + 1u + hy2; if (i21 >= size) i21 -= size;
                i22 = ix + 2u + hy2; if (i22 >= size) i22 -= size;
            }

            const u64* tb = (const u64*)(table + off);
            u64 T00 = __ldg(tb + i00);
            u64 T01 = __ldg(tb + i01);
            u64 T10 = __ldg(tb + i10);
            u64 T11 = __ldg(tb + i11);
            u64 T02 = 0ull, T12 = 0ull, T20 = 0ull, T21 = 0ull, T22 = 0ull;
            if (bdx) { T02 = __ldg(tb + i02); T12 = __ldg(tb + i12); }
            if (bdy) { T20 = __ldg(tb + i20); T21 = __ldg(tb + i21); }
            if (bdx && bdy) { T22 = __ldg(tb + i22); }

            u64 ua0p = pk2(ua0, ua0), ua1p = pk2(ua1, ua1);
            u64 ub0p = pk2(ub0, ub0), ub1p = pk2(ub1, ub1);
            u64 va0p = pk2(va0, va0), va1p = pk2(va1, va1);
            u64 vb0p = pk2(vb0, vb0), vb1p = pk2(vb1, vb1);

            u64 S00 = ffma2(ua1p, T01, mul2(ua0p, T00));
            u64 S01 = ffma2(ua1p, T11, mul2(ua0p, T10));
            u64 S02 = ffma2(ua1p, T21, mul2(ua0p, T20));
            u64 X0r0 = bdx ? T01 : T00, X1r0 = bdx ? T02 : T01;
            u64 X0r1 = bdx ? T11 : T10, X1r1 = bdx ? T12 : T11;
            u64 X0r2 = bdx ? T21 : T20, X1r2 = bdx ? T22 : T21;
            u64 S10 = ffma2(ub1p, X1r0, mul2(ub0p, X0r0));
            u64 S11 = ffma2(ub1p, X1r1, mul2(ub0p, X0r1));
            u64 S12 = ffma2(ub1p, X1r2, mul2(ub0p, X0r2));

            Pa[li] = cvt_h2(ffma2(va1p, S01, mul2(va0p, S00)));
            Pb[li] = cvt_h2(ffma2(va1p, S11, mul2(va0p, S10)));
            u64 Y0a = bdy ? S01 : S00, Y1a = bdy ? S02 : S01;
            u64 Y0b = bdy ? S11 : S10, Y1b = bdy ? S12 : S11;
            Pc[li] = cvt_h2(ffma2(vb1p, Y1a, mul2(vb0p, Y0a)));
            Pd[li] = cvt_h2(ffma2(vb1p, Y1b, mul2(vb0p, Y0b)));
        }
        *(uint4*)(myA + (0 * 32 + lid) * A_STRIDE_H + lg * 8) = make_uint4(Pa[0], Pa[1], Pa[2], Pa[3]);
        *(uint4*)(myA + (1 * 32 + lid) * A_STRIDE_H + lg * 8) = make_uint4(Pb[0], Pb[1], Pb[2], Pb[3]);
        *(uint4*)(myA + (2 * 32 + lid) * A_STRIDE_H + lg * 8) = make_uint4(Pc[0], Pc[1], Pc[2], Pc[3]);
        *(uint4*)(myA + (3 * 32 + lid) * A_STRIDE_H + lg * 8) = make_uint4(Pd[0], Pd[1], Pd[2], Pd[3]);
    }
    __syncwarp();

    // Layer-1 B fragments (W0^T), per mma m16n8k16 spec; conflict-free.
    u32 Bf[2][8][2];
    #pragma unroll
    for (int kc = 0; kc < 2; kc++) {
        #pragma unroll
        for (int nt = 0; nt < 8; nt++) {
            const u32* wrow = (const u32*)&sW0h[(nt * 8 + g) * W_STRIDE_H + kc * 16];
            Bf[kc][nt][0] = wrow[tig];
            Bf[kc][nt][1] = wrow[tig + 4];
        }
    }
    // Layer-2 B fragments (m16n8k8): Bf2[nt] = {w1[g][8nt+2tig], w1[g][8nt+2tig+1]}
    u32 Bf2[8];
    #pragma unroll
    for (int nt = 0; nt < 8; nt++)
        Bf2[nt] = *(const u32*)&sW1h[g * 64 + nt * 8 + tig * 2];

    float cw[4];
    cw[0] = (1.0f - u) * (1.0f - v) * INV_FSCALE;
    cw[1] = u * (1.0f - v) * INV_FSCALE;
    cw[2] = (1.0f - u) * v * INV_FSCALE;
    cw[3] = u * v * INV_FSCALE;

    const int base = blockIdx.x * 128 + wid * 32;

    #pragma unroll
    for (int mtp = 0; mtp < 2; mtp++) {
        float hb[8][4];
        #pragma unroll
        for (int b = 0; b < 8; b++)
            #pragma unroll
            for (int c = 0; c < 4; c++) hb[b][c] = 0.0f;

        #pragma unroll
        for (int c = 0; c < 4; c++) {
            // D rows g / g+8 belong to points mtp*16+g / +8 -> fetch their blend
            // weights via shfl.
            float wlo = __shfl_sync(0xffffffffu, cw[c], mtp * 16 + g);
            float whi = __shfl_sync(0xffffffffu, cw[c], mtp * 16 + g + 8);

            u32 afr[2][4];
            #pragma unroll
            for (int kc = 0; kc < 2; kc++) {
                const __half* ar =
                    myA + (c * 32 + mtp * 16 + g) * A_STRIDE_H + kc * 16 + tig * 2;
                afr[kc][0] = *(const u32*)(ar);
                afr[kc][1] = *(const u32*)(ar + 8 * A_STRIDE_H);
                afr[kc][2] = *(const u32*)(ar + 8);
                afr[kc][3] = *(const u32*)(ar + 8 * A_STRIDE_H + 8);
            }
            #pragma unroll
            for (int nt = 0; nt < 8; nt++) {
                float d0 = 0.0f, d1 = 0.0f, d2 = 0.0f, d3 = 0.0f;
                asm volatile("mma.sync.aligned.m16n8k16.row.col.f32.f16.f16.f32 "
                    "{%0,%1,%2,%3},{%4,%5,%6,%7},{%8,%9},{%0,%1,%2,%3};"
                    : "+f"(d0), "+f"(d1), "+f"(d2), "+f"(d3)
                    : "r"(afr[0][0]), "r"(afr[0][1]), "r"(afr[0][2]), "r"(afr[0][3]),
                      "r"(Bf[0][nt][0]), "r"(Bf[0][nt][1]));
                asm volatile("mma.sync.aligned.m16n8k16.row.col.f32.f16.f16.f32 "
                    "{%0,%1,%2,%3},{%4,%5,%6,%7},{%8,%9},{%0,%1,%2,%3};"
                    : "+f"(d0), "+f"(d1), "+f"(d2), "+f"(d3)
                    : "r"(afr[1][0]), "r"(afr[1][1]), "r"(afr[1][2]), "r"(afr[1][3]),
                      "r"(Bf[1][nt][0]), "r"(Bf[1][nt][1]));
                hb[nt][0] = fmaf(fmaxf(d0, 0.0f), wlo, hb[nt][0]);
                hb[nt][1] = fmaf(fmaxf(d1, 0.0f), wlo, hb[nt][1]);
                hb[nt][2] = fmaf(fmaxf(d2, 0.0f), whi, hb[nt][2]);
                hb[nt][3] = fmaf(fmaxf(d3, 0.0f), whi, hb[nt][3]);
            }
        }

        // Layer 2 as MMA (m16n8k8): hblend D-fragments become A-fragments
        // in-register; output D-fragment goes straight to gmem.
        float o0 = 0.0f, o1 = 0.0f, o2 = 0.0f, o3 = 0.0f;
        #pragma unroll
        for (int nt = 0; nt < 8; nt++) {
            u32 a0 = cvt_h2f(hb[nt][0], hb[nt][1]);
            u32 a1 = cvt_h2f(hb[nt][2], hb[nt][3]);
            asm volatile("mma.sync.aligned.m16n8k8.row.col.f32.f16.f16.f32 "
                "{%0,%1,%2,%3},{%4,%5},{%6},{%0,%1,%2,%3};"
                : "+f"(o0), "+f"(o1), "+f"(o2), "+f"(o3)
                : "r"(a0), "r"(a1), "r"(Bf2[nt]));
        }

        int pt0 = base + mtp * 16 + g;
        if (pt0 < N)
            *(float2*)(out + (size_t)pt0 * 8 + 2 * tig) = make_float2(o0, o1);
        int pt1 = pt0 + 8;
        if (pt1 < N)
            *(float2*)(out + (size_t)pt1 * 8 + 2 * tig) = make_float2(o2, o3);
    }
}

extern "C" void kernel_launch(void* const* d_in, const int* in_sizes, int n_in,
                              void* d_out, int out_size)
{
    const float2* xy    = (const float2*)d_in[0];
    const float2* table = (const float2*)d_in[1];
    const float*  w0    = (const float*)d_in[2];
    const float*  w1    = (const float*)d_in[3];
    const unsigned* bound = (n_in > 4) ? (const unsigned*)d_in[4] : nullptr;
    int bound_elems = (n_in > 4) ? in_sizes[4] : 0;

    int N = in_sizes[0] / 2;

    // Level constants — same double-precision libm sequence as the numpy
    // reference so ceil() boundaries match exactly.
    Levels L;
    double b = exp2(log2(2048.0 / 16.0) / 15.0);
    unsigned off = 0;
    for (int l = 0; l < NLEV; l++) {
        double s = 16.0 * pow(b, (double)l) - 1.0;
        int r = (int)ceil(s) + 1;
        unsigned long long pp = (unsigned long long)r * (unsigned long long)r;
        unsigned psz = (pp > (unsigned long long)(1u << 19)) ? (1u << 19) : (unsigned)pp;
        psz = (psz + 7u) / 8u * 8u;
        L.scale[l]  = (float)s;
        L.res[l]    = (unsigned)r;
        L.size[l]   = psz;
        L.offset[l] = off;
        L.hashed[l] = (pp > (unsigned long long)psz) ? 1u : 0u;
        off += psz;
    }

    int blocks = (N + 127) / 128;
    plane_kernel<<<blocks, 128>>>(xy, table, w0, w1, bound, bound_elems,
                                  (float*)d_out, N, L);
}